// round 4
// baseline (speedup 1.0000x reference)
#include <cuda_runtime.h>

#define NN 262144
#define EGG_MAX 4000000
#define E2_MAX  2000000

// ---------------- static device scratch (no allocs allowed) ----------------
__device__ int g_is64;  // 1 if edge buffers are int64, 0 if int32
// CSR structures
__device__ __align__(16) int g_deg_gg[NN], g_deg_h[NN], g_deg_in[NN], g_deg_ss[NN];
__device__ __align__(16) int g_rp_gg[NN],  g_rp_h[NN],  g_rp_in[NN],  g_rp_ss[NN];
__device__ __align__(16) int g_cur_gg[NN], g_cur_h[NN], g_cur_in[NN], g_cur_ss[NN];
__device__ int g_bsum[512];
__device__ __align__(16) int g_adj_gg[EGG_MAX];
__device__ __align__(16) int g_adj_h[E2_MAX];
__device__ __align__(16) int g_adj_in[E2_MAX];
__device__ __align__(16) int g_adj_ss[E2_MAX];
__device__ __align__(16) float g_wadj_h[E2_MAX];
// derived per-node scalars
__device__ __align__(16) float g_dinv_gg[NN], g_dinv_ss[NN], g_cntf[NN];
// feature scratch
__device__ __align__(16) float g_h1[NN * 5];
__device__ __align__(16) float g_h2[NN * 5];
__device__ __align__(16) float g_gamex[(size_t)NN * 64];
__device__ __align__(16) float g_agg[(size_t)NN * 64];
__device__ __align__(16) float g_sum[(size_t)NN * 64];
__device__ __align__(16) float g_s1[(size_t)NN * 64];
__device__ __align__(16) float g_s2[(size_t)NN * 64];
__device__ __align__(16) float g_t1[(size_t)NN * 64];
__device__ __align__(16) float g_t2[(size_t)NN * 64];
__device__ __align__(16) float g_t3[(size_t)NN * 64];

// ---------------- dtype probe: int64 indices < 2^18 have zero high words ----------------
__global__ void probe_kernel(const unsigned long long* __restrict__ e) {
    // single thread, 256 samples; all-high-zero => int64
    if (threadIdx.x == 0 && blockIdx.x == 0) {
        int is64 = 1;
        for (int j = 0; j < 256; j++)
            if ((e[j] >> 32) != 0ull) { is64 = 0; break; }
        g_is64 = is64;
    }
}

__device__ __forceinline__ bool load_edge(const void* ei, int E, int e, int is64,
                                          int& row, int& col) {
    if (is64) {
        const long long* p = (const long long*)ei;
        long long r = p[e], c = p[(size_t)E + e];
        row = (int)r; col = (int)c;
        return ((unsigned long long)r < NN) && ((unsigned long long)c < NN);
    } else {
        const int* p = (const int*)ei;
        row = p[e]; col = p[(size_t)E + e];
        return ((unsigned)row < NN) && ((unsigned)col < NN);
    }
}

// ---------------- zero degree + cursor arrays (one launch) ----------------
__global__ void zero_kernel() {
    int i = blockIdx.x * blockDim.x + threadIdx.x;   // 0 .. NN/4-1
    int4 z = make_int4(0, 0, 0, 0);
    ((int4*)g_deg_gg)[i] = z; ((int4*)g_deg_h)[i]  = z;
    ((int4*)g_deg_in)[i] = z; ((int4*)g_deg_ss)[i] = z;
    ((int4*)g_cur_gg)[i] = z; ((int4*)g_cur_h)[i]  = z;
    ((int4*)g_cur_in)[i] = z; ((int4*)g_cur_ss)[i] = z;
}

// ---------------- degree count (by col) ----------------
__global__ void deg_kernel(const void* __restrict__ ei, int E, int* __restrict__ deg) {
    int e = blockIdx.x * blockDim.x + threadIdx.x;
    if (e >= E) return;
    int row, col;
    if (load_edge(ei, E, e, g_is64, row, col))
        atomicAdd(deg + col, 1);
}

// ---------------- exclusive scan over NN = 512*512 ----------------
__global__ void scan1_kernel(const int* __restrict__ deg, int* __restrict__ rp, int* __restrict__ bsum) {
    __shared__ int s[512];
    int i = blockIdx.x * 512 + threadIdx.x;
    int v = deg[i];
    s[threadIdx.x] = v;
    __syncthreads();
#pragma unroll
    for (int off = 1; off < 512; off <<= 1) {
        int t = (threadIdx.x >= off) ? s[threadIdx.x - off] : 0;
        __syncthreads();
        s[threadIdx.x] += t;
        __syncthreads();
    }
    rp[i] = s[threadIdx.x] - v;
    if (threadIdx.x == 511) bsum[blockIdx.x] = s[511];
}

__global__ void scan2_kernel(int* __restrict__ bsum) {   // 1 block, 512 threads
    __shared__ int s[512];
    int v = bsum[threadIdx.x];
    s[threadIdx.x] = v;
    __syncthreads();
#pragma unroll
    for (int off = 1; off < 512; off <<= 1) {
        int t = (threadIdx.x >= off) ? s[threadIdx.x - off] : 0;
        __syncthreads();
        s[threadIdx.x] += t;
        __syncthreads();
    }
    bsum[threadIdx.x] = s[threadIdx.x] - v;
}

__global__ void scan3_kernel(int* __restrict__ rp, const int* __restrict__ bsum) {
    int i = blockIdx.x * 512 + threadIdx.x;
    rp[i] += bsum[blockIdx.x];
}

// ---------------- CSR fill ----------------
__global__ void fill_kernel(const void* __restrict__ ei, int E,
                            const int* __restrict__ rp, int* __restrict__ cur,
                            int* __restrict__ adj, float* __restrict__ wadj,
                            const float* __restrict__ ew) {
    int e = blockIdx.x * blockDim.x + threadIdx.x;
    if (e >= E) return;
    int row, col;
    if (!load_edge(ei, E, e, g_is64, row, col)) return;
    int pos = atomicAdd(cur + col, 1);
    int slot = rp[col] + pos;
    adj[slot] = row;
    if (wadj) wadj[slot] = ew[e];
}

// ---------------- per-node scalars ----------------
__global__ void prep_kernel() {
    int i = blockIdx.x * blockDim.x + threadIdx.x;
    if (i >= NN) return;
    int d = g_deg_gg[i];
    g_dinv_gg[i] = d > 0 ? rsqrtf((float)d) : 0.f;
    d = g_deg_ss[i];
    g_dinv_ss[i] = d > 0 ? rsqrtf((float)d) : 0.f;
    g_cntf[i] = (float)g_deg_in[i];
}

// ---------------- D=5 gather hop (TAGConv1): out[n] = sum_e dinv[src]*dinv[n]*in[src] ------------
__global__ void gather5_kernel(const int* __restrict__ rp, const int* __restrict__ deg,
                               const int* __restrict__ adj, const float* __restrict__ dinv,
                               const float* __restrict__ in, float* __restrict__ out) {
    int gid = blockIdx.x * blockDim.x + threadIdx.x;
    int n = gid >> 3;
    int sub = gid & 7;
    if (n >= NN) return;
    int base = rp[n];
    int d = deg[n];
    float dn = dinv[n];
    float acc = 0.f;
    for (int j = 0; j < d; j++) {
        int src = adj[base + j];
        float w = dinv[src] * dn;
        if (sub < 5) acc += w * in[(size_t)src * 5 + sub];
    }
    if (sub < 5) out[(size_t)n * 5 + sub] = acc;
}

// ---------------- D=64 gather: warp per node. MODE 0=sym-norm, 1=edge weight, 2=plain sum -------
template <int MODE>
__global__ void gather64_kernel(const int* __restrict__ rp, const int* __restrict__ deg,
                                const int* __restrict__ adj, const float* __restrict__ wadj,
                                const float* __restrict__ dinv,
                                const float* __restrict__ in, float* __restrict__ out) {
    int warp = (blockIdx.x * blockDim.x + threadIdx.x) >> 5;
    int lane = threadIdx.x & 31;
    if (warp >= NN) return;
    int base = rp[warp];
    int d = deg[warp];
    float dn = (MODE == 0) ? dinv[warp] : 0.f;
    float2 acc = make_float2(0.f, 0.f);
    const float2* inp = (const float2*)in;
    for (int j = 0; j < d; j++) {
        int src = adj[base + j];
        float w = 1.f;
        if (MODE == 0) w = dinv[src] * dn;
        if (MODE == 1) w = wadj[base + j];
        float2 v = inp[(size_t)src * 32 + lane];
        acc.x = fmaf(w, v.x, acc.x);
        acc.y = fmaf(w, v.y, acc.y);
    }
    ((float2*)out)[(size_t)warp * 32 + lane] = acc;
}

// ---------------- generic combine: out = relu(bias + sum_s A_s @ W_s) [optional final 64->8] -----
struct CombineParams {
    const float* A0; const float* A1; const float* A2; const float* A3;
    const float* W0; const float* W1; const float* W2; const float* W3;
    const float* bias;
    const float* cnt;    // SCALE0: A0 rows scaled by 1/max(cnt,1)
    const float* finW;   // FINAL8: [64][8]
    const float* finB;   // FINAL8: [8]
    float* out;
};

template <int NS, int D0, int D1, int D2, int D3, bool SCALE0, bool FINAL8>
__global__ void __launch_bounds__(256) combine_kernel(CombineParams p) {
    __shared__ float Asm[64][65];   // [node][k], pitch 65 -> conflict-free
    __shared__ float Wsm[64][64];   // [k][h]
    const int tid = threadIdx.x;
    const int tx = tid & 15;        // h-group
    const int ty = tid >> 4;        // node lane base
    const int h4 = tx * 4;
    const int nbase = blockIdx.x * 64;

    float acc[4][4];
    {
        float b0 = p.bias[h4 + 0], b1 = p.bias[h4 + 1], b2 = p.bias[h4 + 2], b3 = p.bias[h4 + 3];
#pragma unroll
        for (int i = 0; i < 4; i++) { acc[i][0] = b0; acc[i][1] = b1; acc[i][2] = b2; acc[i][3] = b3; }
    }

#pragma unroll
    for (int s = 0; s < NS; s++) {
        const int D = (s == 0) ? D0 : (s == 1) ? D1 : (s == 2) ? D2 : D3;
        const float* A = (s == 0) ? p.A0 : (s == 1) ? p.A1 : (s == 2) ? p.A2 : p.A3;
        const float* W = (s == 0) ? p.W0 : (s == 1) ? p.W1 : (s == 2) ? p.W2 : p.W3;
        for (int i = tid; i < D * 64; i += 256) Wsm[i >> 6][i & 63] = W[i];
        for (int i = tid; i < 64 * D; i += 256) {
            int n = i / D, k = i - n * D;
            float v = A[(size_t)(nbase + n) * D + k];
            if (SCALE0 && s == 0) v *= (1.0f / fmaxf(p.cnt[nbase + n], 1.0f));
            Asm[n][k] = v;
        }
        __syncthreads();
#pragma unroll 4
        for (int k = 0; k < D; k++) {
            const float4 w = *(const float4*)&Wsm[k][h4];
#pragma unroll
            for (int i = 0; i < 4; i++) {
                const float a = Asm[ty + 16 * i][k];
                acc[i][0] = fmaf(a, w.x, acc[i][0]);
                acc[i][1] = fmaf(a, w.y, acc[i][1]);
                acc[i][2] = fmaf(a, w.z, acc[i][2]);
                acc[i][3] = fmaf(a, w.w, acc[i][3]);
            }
        }
        __syncthreads();
    }

#pragma unroll
    for (int i = 0; i < 4; i++)
#pragma unroll
        for (int j = 0; j < 4; j++) acc[i][j] = fmaxf(acc[i][j], 0.0f);

    if (!FINAL8) {
#pragma unroll
        for (int i = 0; i < 4; i++) {
            size_t n = (size_t)nbase + ty + 16 * i;
            *(float4*)&p.out[n * 64 + h4] = make_float4(acc[i][0], acc[i][1], acc[i][2], acc[i][3]);
        }
    } else {
#pragma unroll
        for (int i = 0; i < 4; i++) {
            int n = ty + 16 * i;
            Asm[n][h4 + 0] = acc[i][0];
            Asm[n][h4 + 1] = acc[i][1];
            Asm[n][h4 + 2] = acc[i][2];
            Asm[n][h4 + 3] = acc[i][3];
        }
        __syncthreads();
        for (int idx = tid; idx < 512; idx += 256) {
            int n = idx >> 3, o = idx & 7;
            float v = p.finB[o];
#pragma unroll
            for (int k = 0; k < 64; k++) v = fmaf(Asm[n][k], p.finW[k * 8 + o], v);
            p.out[(size_t)(nbase + n) * 8 + o] = v;
        }
    }
}

// ---------------- launch ----------------
static void build_csr(const void* ei, int E, int* deg, int* rp, int* cur,
                      int* adj, float* wadj, const float* ew, int* bsum) {
    deg_kernel<<<(E + 255) / 256, 256>>>(ei, E, deg);
    scan1_kernel<<<512, 512>>>(deg, rp, bsum);
    scan2_kernel<<<1, 512>>>(bsum);
    scan3_kernel<<<512, 512>>>(rp, bsum);
    fill_kernel<<<(E + 255) / 256, 256>>>(ei, E, rp, cur, adj, wadj, ew);
}

extern "C" void kernel_launch(void* const* d_in, const int* in_sizes, int n_in,
                              void* d_out, int out_size) {
    const float* x_game   = (const float*)d_in[0];
    const float* x_state  = (const float*)d_in[1];
    const void*  e_gg     = d_in[2];
    const void*  e_hist   = d_in[3];
    const void*  e_in     = d_in[4];
    const void*  e_ss     = d_in[5];
    const float* ew_hist  = (const float*)d_in[6];
    const float* tag1_w   = (const float*)d_in[7];
    const float* tag1_b   = (const float*)d_in[8];
    const float* tag2_w   = (const float*)d_in[9];
    const float* tag2_b   = (const float*)d_in[10];
    const float* gc_w_rel = (const float*)d_in[11];
    const float* gc_b_rel = (const float*)d_in[12];
    const float* gc_w_root= (const float*)d_in[13];
    const float* sage_w_l = (const float*)d_in[14];
    const float* sage_b_l = (const float*)d_in[15];
    const float* sage_w_r = (const float*)d_in[16];
    const float* lin_w    = (const float*)d_in[17];
    const float* lin_b    = (const float*)d_in[18];
    float* out = (float*)d_out;

    const int Egg = in_sizes[2] / 2;
    const int Eh  = in_sizes[3] / 2;
    const int Ein = in_sizes[4] / 2;
    const int Ess = in_sizes[5] / 2;

#define SYM(p, s) cudaGetSymbolAddress((void**)&p, s)
    int *p_deg_gg, *p_deg_h, *p_deg_in, *p_deg_ss;
    int *p_rp_gg, *p_rp_h, *p_rp_in, *p_rp_ss;
    int *p_cur_gg, *p_cur_h, *p_cur_in, *p_cur_ss;
    int *p_adj_gg, *p_adj_h, *p_adj_in, *p_adj_ss, *p_bsum;
    float *p_wadj_h, *p_dinv_gg, *p_dinv_ss, *p_cntf;
    float *p_h1, *p_h2, *p_gamex, *p_agg, *p_sum, *p_s1, *p_s2, *p_t1, *p_t2, *p_t3;
    SYM(p_deg_gg, g_deg_gg); SYM(p_deg_h, g_deg_h); SYM(p_deg_in, g_deg_in); SYM(p_deg_ss, g_deg_ss);
    SYM(p_rp_gg, g_rp_gg);   SYM(p_rp_h, g_rp_h);   SYM(p_rp_in, g_rp_in);   SYM(p_rp_ss, g_rp_ss);
    SYM(p_cur_gg, g_cur_gg); SYM(p_cur_h, g_cur_h); SYM(p_cur_in, g_cur_in); SYM(p_cur_ss, g_cur_ss);
    SYM(p_adj_gg, g_adj_gg); SYM(p_adj_h, g_adj_h); SYM(p_adj_in, g_adj_in); SYM(p_adj_ss, g_adj_ss);
    SYM(p_bsum, g_bsum);     SYM(p_wadj_h, g_wadj_h);
    SYM(p_dinv_gg, g_dinv_gg); SYM(p_dinv_ss, g_dinv_ss); SYM(p_cntf, g_cntf);
    SYM(p_h1, g_h1); SYM(p_h2, g_h2); SYM(p_gamex, g_gamex); SYM(p_agg, g_agg);
    SYM(p_sum, g_sum); SYM(p_s1, g_s1); SYM(p_s2, g_s2);
    SYM(p_t1, g_t1); SYM(p_t2, g_t2); SYM(p_t3, g_t3);
#undef SYM

    // 0. dtype probe (on edge_gg; all edge buffers share a dtype)
    probe_kernel<<<1, 32>>>((const unsigned long long*)e_gg);

    // 1. zero degree/cursor arrays
    zero_kernel<<<NN / 4 / 256, 256>>>();

    // 2. build 4 CSRs
    build_csr(e_gg,   Egg, p_deg_gg, p_rp_gg, p_cur_gg, p_adj_gg, nullptr,  nullptr, p_bsum);
    build_csr(e_hist, Eh,  p_deg_h,  p_rp_h,  p_cur_h,  p_adj_h,  p_wadj_h, ew_hist, p_bsum);
    build_csr(e_in,   Ein, p_deg_in, p_rp_in, p_cur_in, p_adj_in, nullptr,  nullptr, p_bsum);
    build_csr(e_ss,   Ess, p_deg_ss, p_rp_ss, p_cur_ss, p_adj_ss, nullptr,  nullptr, p_bsum);

    // 3. per-node scalars
    prep_kernel<<<NN / 256, 256>>>();

    // 4. TAGConv1 hops (D=5 gathers) + combine -> game_x
    gather5_kernel<<<NN * 8 / 256, 256>>>(p_rp_gg, p_deg_gg, p_adj_gg, p_dinv_gg, x_game, p_h1);
    gather5_kernel<<<NN * 8 / 256, 256>>>(p_rp_gg, p_deg_gg, p_adj_gg, p_dinv_gg, p_h1, p_h2);
    {
        CombineParams p{};
        p.A0 = x_game; p.A1 = p_h1; p.A2 = p_h2;
        p.W0 = tag1_w; p.W1 = tag1_w + 5 * 64; p.W2 = tag1_w + 10 * 64;
        p.bias = tag1_b; p.out = p_gamex;
        combine_kernel<3, 5, 5, 5, 5, false, false><<<NN / 64, 256>>>(p);
    }

    // 5. GraphConv: weighted gather + combine -> s1
    gather64_kernel<1><<<NN * 32 / 256, 256>>>(p_rp_h, p_deg_h, p_adj_h, p_wadj_h, nullptr, p_gamex, p_agg);
    {
        CombineParams p{};
        p.A0 = p_agg; p.A1 = x_state;
        p.W0 = gc_w_rel; p.W1 = gc_w_root;
        p.bias = gc_b_rel; p.out = p_s1;
        combine_kernel<2, 64, 6, 1, 1, false, false><<<NN / 64, 256>>>(p);
    }

    // 6. SAGEConv: sum gather + mean-combine -> s2
    gather64_kernel<2><<<NN * 32 / 256, 256>>>(p_rp_in, p_deg_in, p_adj_in, nullptr, nullptr, p_gamex, p_sum);
    {
        CombineParams p{};
        p.A0 = p_sum; p.A1 = p_s1;
        p.W0 = sage_w_l; p.W1 = sage_w_r;
        p.bias = sage_b_l; p.cnt = p_cntf; p.out = p_s2;
        combine_kernel<2, 64, 64, 1, 1, true, false><<<NN / 64, 256>>>(p);
    }

    // 7. TAGConv2 hops (D=64, K=3) + combine fused with final 64->8 linear -> out
    gather64_kernel<0><<<NN * 32 / 256, 256>>>(p_rp_ss, p_deg_ss, p_adj_ss, nullptr, p_dinv_ss, p_s2, p_t1);
    gather64_kernel<0><<<NN * 32 / 256, 256>>>(p_rp_ss, p_deg_ss, p_adj_ss, nullptr, p_dinv_ss, p_t1, p_t2);
    gather64_kernel<0><<<NN * 32 / 256, 256>>>(p_rp_ss, p_deg_ss, p_adj_ss, nullptr, p_dinv_ss, p_t2, p_t3);
    {
        CombineParams p{};
        p.A0 = p_s2; p.A1 = p_t1; p.A2 = p_t2; p.A3 = p_t3;
        p.W0 = tag2_w; p.W1 = tag2_w + 4096; p.W2 = tag2_w + 2 * 4096; p.W3 = tag2_w + 3 * 4096;
        p.bias = tag2_b; p.finW = lin_w; p.finB = lin_b; p.out = out;
        combine_kernel<4, 64, 64, 64, 64, false, true><<<NN / 64, 256>>>(p);
    }
}